// round 1
// baseline (speedup 1.0000x reference)
#include <cuda_runtime.h>
#include <math.h>

// Problem constants
#define D 768
#define B 512

// GEMM tiling
#define BM 64
#define BN 64
#define BK 16
#define KSPLIT 2
#define KCHUNK (D / KSPLIT)   // 384

// Scratch: logits[b*2 + k]  (device global: allocation-free scratch)
__device__ float g_logits[B * 2];

// ---------------------------------------------------------------------------
// Kernel 1: initialize logits with the bias
// ---------------------------------------------------------------------------
__global__ void init_logits_kernel(const float* __restrict__ fc_b) {
    int i = blockIdx.x * blockDim.x + threadIdx.x;
    if (i < B * 2) g_logits[i] = fc_b[i & 1];
}

// ---------------------------------------------------------------------------
// Kernel 2: fused GEMM + dot-reduce.
//   C[b, i'] = sum_j s_x[b, j] * Wcat[i', j]      (i' in [0, 1536))
//   logits[b, k] += sum_i v_x[b, i] * C[b, k*768 + i]
// C tiles are consumed in-register; never written to global.
// Grid: (1536/BN, 512/BM, KSPLIT); 256 threads; 4x4 register tile per thread.
// ---------------------------------------------------------------------------
__global__ __launch_bounds__(256, 4)
void gemm_dot_kernel(const float* __restrict__ S,    // s_x  [B][D]
                     const float* __restrict__ Wc,   // fc_w [2*D][D]
                     const float* __restrict__ V)    // v_x  [B][D]
{
    __shared__ float As[BK][BM + 4];   // S tile, transposed: As[k][m]
    __shared__ float Bs[BK][BN + 4];   // W tile, transposed: Bs[k][n]
    __shared__ float rowAcc[BM];

    const int tid = threadIdx.x;
    const int tx  = tid & 15;          // column group (0..15) -> cols tx*4..+3
    const int ty  = tid >> 4;          // row group    (0..15) -> rows ty*4..+3

    const int rowBase = blockIdx.y * BM;       // b base
    const int colBase = blockIdx.x * BN;       // i' base (0..1535)
    const int kBase   = blockIdx.z * KCHUNK;   // j base

    // Per-thread global-load assignment: one float4 of each operand per BK step
    const int lrow = tid >> 2;                 // 0..63
    const int lcg  = (tid & 3) * 4;            // 0,4,8,12

    const float* Sload = S  + (rowBase + lrow) * D + kBase + lcg;
    const float* Wload = Wc + (size_t)(colBase + lrow) * D + kBase + lcg;

    float acc[4][4] = {};

    for (int kk = 0; kk < KCHUNK; kk += BK) {
        float4 sa = *(const float4*)(Sload + kk);
        float4 wb = *(const float4*)(Wload + kk);
        As[lcg + 0][lrow] = sa.x;
        As[lcg + 1][lrow] = sa.y;
        As[lcg + 2][lrow] = sa.z;
        As[lcg + 3][lrow] = sa.w;
        Bs[lcg + 0][lrow] = wb.x;
        Bs[lcg + 1][lrow] = wb.y;
        Bs[lcg + 2][lrow] = wb.z;
        Bs[lcg + 3][lrow] = wb.w;
        __syncthreads();

        #pragma unroll
        for (int k = 0; k < BK; k++) {
            float4 a4 = *(const float4*)&As[k][ty * 4];
            float4 b4 = *(const float4*)&Bs[k][tx * 4];
            float av[4] = {a4.x, a4.y, a4.z, a4.w};
            float bv[4] = {b4.x, b4.y, b4.z, b4.w};
            #pragma unroll
            for (int m = 0; m < 4; m++) {
                #pragma unroll
                for (int n = 0; n < 4; n++) {
                    acc[m][n] = fmaf(av[m], bv[n], acc[m][n]);
                }
            }
        }
        __syncthreads();
    }

    // Epilogue: dot each C row-fragment with the matching v_x fragment,
    // reduce within the block, atomically accumulate into logits.
    const int kIdx  = colBase / D;     // which W head (0 or 1)
    const int iBase = colBase % D;     // i offset within the head

    if (tid < BM) rowAcc[tid] = 0.0f;
    __syncthreads();

    #pragma unroll
    for (int m = 0; m < 4; m++) {
        int grow = rowBase + ty * 4 + m;
        float4 v4 = *(const float4*)(V + grow * D + iBase + tx * 4);
        float s = acc[m][0] * v4.x + acc[m][1] * v4.y
                + acc[m][2] * v4.z + acc[m][3] * v4.w;
        atomicAdd(&rowAcc[ty * 4 + m], s);
    }
    __syncthreads();

    if (tid < BM) {
        atomicAdd(&g_logits[(rowBase + tid) * 2 + kIdx], rowAcc[tid]);
    }
}

// ---------------------------------------------------------------------------
// Kernel 3: softmax over the 2 logits + fused combine. float4 vectorized.
// ---------------------------------------------------------------------------
__global__ __launch_bounds__(256)
void fuse_kernel(const float* __restrict__ V,
                 const float* __restrict__ S,
                 float* __restrict__ out)
{
    int idx = blockIdx.x * blockDim.x + threadIdx.x;   // float4 index
    if (idx >= B * D / 4) return;
    int b = idx / (D / 4);

    float l0 = g_logits[b * 2 + 0];
    float l1 = g_logits[b * 2 + 1];
    float mx = fmaxf(l0, l1);
    float e0 = expf(l0 - mx);
    float e1 = expf(l1 - mx);
    float inv = 1.0f / (e0 + e1);
    float wa = e0 * inv;
    float wb = e1 * inv;

    float4 v = ((const float4*)V)[idx];
    float4 s = ((const float4*)S)[idx];
    float4 o;
    o.x = wa * v.x + wb * s.x;
    o.y = wa * v.y + wb * s.y;
    o.z = wa * v.z + wb * s.z;
    o.w = wa * v.w + wb * s.w;
    ((float4*)out)[idx] = o;
}

// ---------------------------------------------------------------------------
// Entry point
// ---------------------------------------------------------------------------
extern "C" void kernel_launch(void* const* d_in, const int* in_sizes, int n_in,
                              void* d_out, int out_size) {
    const float* v_x  = (const float*)d_in[0];
    const float* s_x  = (const float*)d_in[1];
    const float* fc_w = (const float*)d_in[2];
    const float* fc_b = (const float*)d_in[3];
    float* out = (float*)d_out;

    init_logits_kernel<<<1, 1024>>>(fc_b);

    dim3 grid(2 * D / BN, B / BM, KSPLIT);   // (24, 8, 2) = 384 blocks
    gemm_dot_kernel<<<grid, 256>>>(s_x, fc_w, v_x);

    int n4 = B * D / 4;
    fuse_kernel<<<(n4 + 255) / 256, 256>>>(v_x, s_x, out);
}

// round 3
// speedup vs baseline: 2.3463x; 2.3463x over previous
#include <cuda_runtime.h>
#include <cuda_bf16.h>
#include <cstdint>
#include <math.h>

#define D 768
#define B 512
#define NTOT (2 * D)          // 1536 rows of concatenated W

// GEMM tiling
#define TM 128
#define TN 128
#define TK 64                 // bf16 elements per K chunk (128 B = SW128 row)
#define STAGES 3
#define KSPLIT 3              // one split term per z: hi*hi, hi*lo, lo*hi
#define CHUNKS_PER (D / TK)   // 12

#define TILE_BYTES 16384               // 128 rows x 128 bytes
#define STAGE_BYTES (2 * TILE_BYTES)   // A + B
#define SMEM_TILES_OFF 1024
#define SMEM_TOTAL (SMEM_TILES_OFF + STAGES * STAGE_BYTES)   // 99328

// ---------------------------------------------------------------------------
// Device scratch (allocation-free)
// ---------------------------------------------------------------------------
__device__ __nv_bfloat16 g_s_hi[B * D];
__device__ __nv_bfloat16 g_s_lo[B * D];
__device__ __nv_bfloat16 g_W_hi[NTOT * D];
__device__ __nv_bfloat16 g_W_lo[NTOT * D];
__device__ float g_logits[B * 2];

// ---------------------------------------------------------------------------
// PTX helpers (sm_80-era only: cp.async, ldmatrix, mma.sync — all legal on
// the plain sm_103 target this harness compiles for)
// ---------------------------------------------------------------------------
__device__ __forceinline__ uint32_t smem_u32(const void* p) {
    uint32_t a;
    asm("{ .reg .u64 t; cvta.to.shared.u64 t, %1; cvt.u32.u64 %0, t; }"
        : "=r"(a) : "l"(p));
    return a;
}

#define SWZ(o) ((o) ^ (((o) >> 3) & 0x70))

__device__ __forceinline__ void cp_async16(uint32_t dst, const void* src) {
    asm volatile("cp.async.cg.shared.global [%0], [%1], 16;"
                 :: "r"(dst), "l"(src));
}
#define CP_COMMIT() asm volatile("cp.async.commit_group;" ::: "memory")
#define CP_WAIT(n)  asm volatile("cp.async.wait_group %0;" :: "n"(n) : "memory")

#define LDSM_X4(r, addr) \
    asm volatile("ldmatrix.sync.aligned.m8n8.x4.shared.b16 {%0,%1,%2,%3}, [%4];" \
                 : "=r"((r)[0]), "=r"((r)[1]), "=r"((r)[2]), "=r"((r)[3]) \
                 : "r"(addr))

#define MMA_BF16(d, a, b0, b1) \
    asm volatile("mma.sync.aligned.m16n8k16.row.col.f32.bf16.bf16.f32 " \
                 "{%0,%1,%2,%3}, {%4,%5,%6,%7}, {%8,%9}, {%0,%1,%2,%3};" \
                 : "+f"((d)[0]), "+f"((d)[1]), "+f"((d)[2]), "+f"((d)[3]) \
                 : "r"((a)[0]), "r"((a)[1]), "r"((a)[2]), "r"((a)[3]), \
                   "r"(b0), "r"(b1))

// ---------------------------------------------------------------------------
// Kernel 1: split fp32 -> bf16 hi/lo for W and s; init logits with bias.
// ---------------------------------------------------------------------------
__global__ __launch_bounds__(256)
void split_kernel(const float4* __restrict__ W4p,
                  const float4* __restrict__ S4p,
                  const float* __restrict__ fc_b) {
    const int W4 = NTOT * D / 4;   // 294912
    const int S4 = B * D / 4;      // 98304
    int g = blockIdx.x * blockDim.x + threadIdx.x;

    if (g < B * 2) g_logits[g] = fc_b[g & 1];
    if (g >= W4 + S4) return;

    float4 x;
    __nv_bfloat16 *hi, *lo;
    int e;
    if (g < W4) { x = W4p[g]; hi = g_W_hi; lo = g_W_lo; e = g * 4; }
    else        { x = S4p[g - W4]; hi = g_s_hi; lo = g_s_lo; e = (g - W4) * 4; }

    float v[4] = {x.x, x.y, x.z, x.w};
    __nv_bfloat16 h[4], l[4];
#pragma unroll
    for (int j = 0; j < 4; j++) {
        h[j] = __float2bfloat16(v[j]);
        l[j] = __float2bfloat16(v[j] - __bfloat162float(h[j]));
    }
    *(__nv_bfloat162*)(hi + e)     = __nv_bfloat162(h[0], h[1]);
    *(__nv_bfloat162*)(hi + e + 2) = __nv_bfloat162(h[2], h[3]);
    *(__nv_bfloat162*)(lo + e)     = __nv_bfloat162(l[0], l[1]);
    *(__nv_bfloat162*)(lo + e + 2) = __nv_bfloat162(l[2], l[3]);
}

// ---------------------------------------------------------------------------
// Stage loader: 256 threads move one 128x64 bf16 A tile + B tile (16 KB each)
// into SW128-swizzled smem via cp.async, one commit_group per stage.
// ---------------------------------------------------------------------------
__device__ __forceinline__ void load_stage(uint32_t sA, uint32_t sB,
                                           const __nv_bfloat16* Asrc,
                                           const __nv_bfloat16* Bsrc,
                                           int rowBase, int colBase, int kOff,
                                           int tid) {
#pragma unroll
    for (int r = 0; r < 4; r++) {
        int c = tid + r * 256;
        int row = c >> 3, col = c & 7;
        uint32_t off = SWZ(row * 128 + col * 16);
        cp_async16(sA + off, Asrc + (size_t)(rowBase + row) * D + kOff + col * 8);
    }
#pragma unroll
    for (int r = 0; r < 4; r++) {
        int c = tid + r * 256;
        int row = c >> 3, col = c & 7;
        uint32_t off = SWZ(row * 128 + col * 16);
        cp_async16(sB + off, Bsrc + (size_t)(colBase + row) * D + kOff + col * 8);
    }
    CP_COMMIT();
}

// ---------------------------------------------------------------------------
// Kernel 2: mma.sync bf16 GEMM (one split term per blockIdx.z) fused with the
// v_x dot-reduce into logits. Grid (12, 4, 3) = 144 CTAs, 256 threads.
// Warp layout: warp_m = wid&1 (64 rows), warp_n = wid>>1 (32 cols).
// ---------------------------------------------------------------------------
__global__ __launch_bounds__(256, 1)
void gemm_dot_kernel(const float* __restrict__ V) {
    extern __shared__ char smem[];
    const uint32_t smem_base = smem_u32(smem);
    float* rowAcc = (float*)smem;              // 128 floats at offset 0 (<1024)

    const int tid  = threadIdx.x;
    const int wid  = tid >> 5;
    const int lane = tid & 31;
    const int warp_m = wid & 1;
    const int warp_n = wid >> 1;

    const int colBase = blockIdx.x * TN;       // 0..1408 within Wcat
    const int rowBase = blockIdx.y * TM;       // 0..384
    const int seg     = blockIdx.z;            // 0: hi*hi, 1: hi*lo, 2: lo*hi
    const __nv_bfloat16* Asrc = (seg < 2) ? g_s_hi : g_s_lo;
    const __nv_bfloat16* Bsrc = (seg == 1) ? g_W_lo : g_W_hi;

    if (tid < TM) rowAcc[tid] = 0.0f;

    // prefetch first two stages
#pragma unroll
    for (int p = 0; p < STAGES - 1; p++) {
        uint32_t sA = smem_base + SMEM_TILES_OFF + p * STAGE_BYTES;
        load_stage(sA, sA + TILE_BYTES, Asrc, Bsrc, rowBase, colBase, p * TK, tid);
    }

    float acc[4][4][4] = {};                   // [m-tile][n-tile][frag]

    // ldmatrix per-thread address components
    const int rowA = lane & 15, colSelA = lane >> 4;
    const int rowB = ((lane >> 4) << 3) + (lane & 7), colSelB = (lane >> 3) & 1;

    for (int it = 0; it < CHUNKS_PER; it++) {
        if (it < CHUNKS_PER - 1) CP_WAIT(1);
        else                     CP_WAIT(0);
        __syncthreads();

        // prefetch chunk it+2 (overwrites buffer consumed at it-1; the
        // syncthreads above guarantees all warps finished compute it-1)
        int nx = it + STAGES - 1;
        if (nx < CHUNKS_PER) {
            uint32_t nA = smem_base + SMEM_TILES_OFF + (nx % STAGES) * STAGE_BYTES;
            load_stage(nA, nA + TILE_BYTES, Asrc, Bsrc, rowBase, colBase, nx * TK, tid);
        }

        const uint32_t sA = smem_base + SMEM_TILES_OFF + (it % STAGES) * STAGE_BYTES;
        const uint32_t sB = sA + TILE_BYTES;

#pragma unroll
        for (int ks = 0; ks < 4; ks++) {
            uint32_t a[4][4];
            uint32_t b[2][4];
#pragma unroll
            for (int mi = 0; mi < 4; mi++) {
                uint32_t addr = sA + SWZ((64 * warp_m + 16 * mi + rowA) * 128
                                         + (2 * ks + colSelA) * 16);
                LDSM_X4(a[mi], addr);
            }
#pragma unroll
            for (int q = 0; q < 2; q++) {
                uint32_t addr = sB + SWZ((32 * warp_n + 16 * q + rowB) * 128
                                         + (2 * ks + colSelB) * 16);
                LDSM_X4(b[q], addr);
            }
#pragma unroll
            for (int mi = 0; mi < 4; mi++)
#pragma unroll
                for (int nj = 0; nj < 4; nj++) {
                    uint32_t b0 = b[nj >> 1][(nj & 1) * 2 + 0];
                    uint32_t b1 = b[nj >> 1][(nj & 1) * 2 + 1];
                    MMA_BF16(acc[mi][nj], a[mi], b0, b1);
                }
        }
    }

    // --- epilogue: C . v_x, reduced into logits ---
    const int iBase = (colBase % D) + 32 * warp_n;
    const int kIdx  = colBase / D;

    float rs[4][2] = {};
#pragma unroll
    for (int mi = 0; mi < 4; mi++) {
        int r0 = rowBase + 64 * warp_m + 16 * mi + (lane >> 2);
#pragma unroll
        for (int nj = 0; nj < 4; nj++) {
            const float2* v0 = (const float2*)(V + (size_t)r0 * D + iBase
                                               + 8 * nj + 2 * (lane & 3));
            const float2* v1 = (const float2*)(V + (size_t)(r0 + 8) * D + iBase
                                               + 8 * nj + 2 * (lane & 3));
            float2 x0 = *v0, x1 = *v1;
            rs[mi][0] = fmaf(acc[mi][nj][0], x0.x, rs[mi][0]);
            rs[mi][0] = fmaf(acc[mi][nj][1], x0.y, rs[mi][0]);
            rs[mi][1] = fmaf(acc[mi][nj][2], x1.x, rs[mi][1]);
            rs[mi][1] = fmaf(acc[mi][nj][3], x1.y, rs[mi][1]);
        }
    }
#pragma unroll
    for (int mi = 0; mi < 4; mi++)
#pragma unroll
        for (int h = 0; h < 2; h++) {
            rs[mi][h] += __shfl_xor_sync(0xffffffff, rs[mi][h], 1);
            rs[mi][h] += __shfl_xor_sync(0xffffffff, rs[mi][h], 2);
        }
    if ((lane & 3) == 0) {
#pragma unroll
        for (int mi = 0; mi < 4; mi++) {
            int lr = 64 * warp_m + 16 * mi + (lane >> 2);
            atomicAdd(&rowAcc[lr],     rs[mi][0]);
            atomicAdd(&rowAcc[lr + 8], rs[mi][1]);
        }
    }
    __syncthreads();
    if (tid < TM)
        atomicAdd(&g_logits[(rowBase + tid) * 2 + kIdx], rowAcc[tid]);
}

// ---------------------------------------------------------------------------
// Kernel 3: softmax(2 logits) + fused combine (float4 vectorized)
// ---------------------------------------------------------------------------
__global__ __launch_bounds__(256)
void fuse_kernel(const float* __restrict__ V,
                 const float* __restrict__ S,
                 float* __restrict__ out) {
    int idx = blockIdx.x * blockDim.x + threadIdx.x;
    if (idx >= B * D / 4) return;
    int b = idx / (D / 4);

    float l0 = g_logits[b * 2 + 0];
    float l1 = g_logits[b * 2 + 1];
    float mx = fmaxf(l0, l1);
    float e0 = expf(l0 - mx);
    float e1 = expf(l1 - mx);
    float inv = 1.0f / (e0 + e1);
    float wa = e0 * inv;
    float wb = e1 * inv;

    float4 v = ((const float4*)V)[idx];
    float4 s = ((const float4*)S)[idx];
    float4 o;
    o.x = wa * v.x + wb * s.x;
    o.y = wa * v.y + wb * s.y;
    o.z = wa * v.z + wb * s.z;
    o.w = wa * v.w + wb * s.w;
    ((float4*)out)[idx] = o;
}

// ---------------------------------------------------------------------------
// Entry point
// ---------------------------------------------------------------------------
extern "C" void kernel_launch(void* const* d_in, const int* in_sizes, int n_in,
                              void* d_out, int out_size) {
    const float* v_x  = (const float*)d_in[0];
    const float* s_x  = (const float*)d_in[1];
    const float* fc_w = (const float*)d_in[2];
    const float* fc_b = (const float*)d_in[3];
    float* out = (float*)d_out;

    cudaFuncSetAttribute(gemm_dot_kernel,
                         cudaFuncAttributeMaxDynamicSharedMemorySize, SMEM_TOTAL);

    // 1) split + bias init
    split_kernel<<<1536, 256>>>((const float4*)fc_w, (const float4*)s_x, fc_b);

    // 2) fused HMMA GEMM + dot-reduce
    dim3 grid(NTOT / TN, B / TM, KSPLIT);   // (12, 4, 3) = 144 CTAs
    gemm_dot_kernel<<<grid, 256, SMEM_TOTAL>>>(v_x);

    // 3) softmax + combine
    int n4 = B * D / 4;
    fuse_kernel<<<(n4 + 255) / 256, 256>>>(v_x, s_x, out);
}

// round 4
// speedup vs baseline: 2.3627x; 1.0070x over previous
#include <cuda_runtime.h>
#include <cuda_bf16.h>
#include <cstdint>
#include <math.h>

#define D 768
#define B 512
#define NTOT (2 * D)            // 1536 rows of concatenated W

// GEMM tiling: CTA 128x256, warp 64x64, K halved per CTA
#define TM 128
#define TN 256
#define TK 64                   // bf16 per chunk (128 B = one swizzled row)
#define STAGES 3
#define KHALF 384
#define CHUNKS_PER (KHALF / TK) // 6
#define NCTA 144                // (6, 4, 6)

#define A_TILE_BYTES 16384      // 128 x 128B
#define B_TILE_BYTES 32768      // 256 x 128B
#define STAGE_BYTES (A_TILE_BYTES + B_TILE_BYTES)
#define SMEM_TILES_OFF 1024
#define SMEM_TOTAL (SMEM_TILES_OFF + STAGES * STAGE_BYTES)   // 148480

// ---------------------------------------------------------------------------
// Device scratch (allocation-free)
// ---------------------------------------------------------------------------
__device__ __nv_bfloat16 g_s_hi[B * D];
__device__ __nv_bfloat16 g_s_lo[B * D];
__device__ __nv_bfloat16 g_W_hi[NTOT * D];
__device__ __nv_bfloat16 g_W_lo[NTOT * D];
__device__ float g_logits[B * 2];
__device__ int   g_sync;

// ---------------------------------------------------------------------------
// PTX helpers (sm_80-era: legal on the plain sm_103 target)
// ---------------------------------------------------------------------------
__device__ __forceinline__ uint32_t smem_u32(const void* p) {
    uint32_t a;
    asm("{ .reg .u64 t; cvta.to.shared.u64 t, %1; cvt.u32.u64 %0, t; }"
        : "=r"(a) : "l"(p));
    return a;
}

#define SWZ(o) ((o) ^ (((o) >> 3) & 0x70))

__device__ __forceinline__ void cp_async16(uint32_t dst, const void* src) {
    asm volatile("cp.async.cg.shared.global [%0], [%1], 16;"
                 :: "r"(dst), "l"(src));
}
#define CP_COMMIT() asm volatile("cp.async.commit_group;" ::: "memory")
#define CP_WAIT(n)  asm volatile("cp.async.wait_group %0;" :: "n"(n) : "memory")

#define LDSM_X4(r, addr) \
    asm volatile("ldmatrix.sync.aligned.m8n8.x4.shared.b16 {%0,%1,%2,%3}, [%4];" \
                 : "=r"((r)[0]), "=r"((r)[1]), "=r"((r)[2]), "=r"((r)[3]) \
                 : "r"(addr))

#define MMA_BF16(d, a, b0, b1) \
    asm volatile("mma.sync.aligned.m16n8k16.row.col.f32.bf16.bf16.f32 " \
                 "{%0,%1,%2,%3}, {%4,%5,%6,%7}, {%8,%9}, {%0,%1,%2,%3};" \
                 : "+f"((d)[0]), "+f"((d)[1]), "+f"((d)[2]), "+f"((d)[3]) \
                 : "r"((a)[0]), "r"((a)[1]), "r"((a)[2]), "r"((a)[3]), \
                   "r"(b0), "r"(b1))

// ---------------------------------------------------------------------------
// Kernel 1: split fp32 -> bf16 hi/lo; 8 floats/thread, 128-bit stores.
// Also: logits = bias, g_sync = 0.
// ---------------------------------------------------------------------------
__global__ __launch_bounds__(256)
void split_kernel(const float4* __restrict__ W4p,
                  const float4* __restrict__ S4p,
                  const float* __restrict__ fc_b) {
    const int WP = NTOT * D / 8;   // 147456 pairs of float4 (W)
    const int SP = B * D / 8;      // 49152 pairs (s)
    int g = blockIdx.x * blockDim.x + threadIdx.x;

    if (g == 0) g_sync = 0;
    if (g < B * 2) g_logits[g] = fc_b[g & 1];
    if (g >= WP + SP) return;

    float4 x0, x1;
    __nv_bfloat16 *hi, *lo;
    int e;
    if (g < WP) { x0 = W4p[2 * g]; x1 = W4p[2 * g + 1]; hi = g_W_hi; lo = g_W_lo; e = g * 8; }
    else {
        int q = g - WP;
        x0 = S4p[2 * q]; x1 = S4p[2 * q + 1]; hi = g_s_hi; lo = g_s_lo; e = q * 8;
    }

    float v[8] = {x0.x, x0.y, x0.z, x0.w, x1.x, x1.y, x1.z, x1.w};
    uint32_t H[4], L[4];
#pragma unroll
    for (int j = 0; j < 4; j++) {
        float a = v[2 * j], bq = v[2 * j + 1];
        __nv_bfloat162 h2 = __floats2bfloat162_rn(a, bq);
        float ra = a  - __bfloat162float(__low2bfloat16(h2));
        float rb = bq - __bfloat162float(__high2bfloat16(h2));
        __nv_bfloat162 l2 = __floats2bfloat162_rn(ra, rb);
        H[j] = *(uint32_t*)&h2;
        L[j] = *(uint32_t*)&l2;
    }
    *(uint4*)(hi + e) = make_uint4(H[0], H[1], H[2], H[3]);
    *(uint4*)(lo + e) = make_uint4(L[0], L[1], L[2], L[3]);
}

// ---------------------------------------------------------------------------
// Stage loader: A tile 128x64 bf16 (16 KB) + B tile 256x64 bf16 (32 KB)
// ---------------------------------------------------------------------------
__device__ __forceinline__ void load_stage(uint32_t sA, uint32_t sB,
                                           const __nv_bfloat16* Asrc,
                                           const __nv_bfloat16* Bsrc,
                                           int rowBase, int colBase, int kOff,
                                           int tid) {
#pragma unroll
    for (int r = 0; r < 4; r++) {
        int c = tid + r * 256;
        int row = c >> 3, col = c & 7;
        uint32_t off = SWZ(row * 128 + col * 16);
        cp_async16(sA + off, Asrc + (size_t)(rowBase + row) * D + kOff + col * 8);
    }
#pragma unroll
    for (int r = 0; r < 8; r++) {
        int c = tid + r * 256;
        int row = c >> 3, col = c & 7;
        uint32_t off = SWZ(row * 128 + col * 16);
        cp_async16(sB + off, Bsrc + (size_t)(colBase + row) * D + kOff + col * 8);
    }
    CP_COMMIT();
}

// ---------------------------------------------------------------------------
// Kernel 2: HMMA GEMM (warp tile 64x64) + v-dot reduce + device-wide barrier
// + softmax/fuse epilogue. Grid (6, 4, 6) = 144 CTAs, 256 threads.
// z: seg = z>>1 (hi*hi / hi*lo / lo*hi), khalf = z&1.
// ---------------------------------------------------------------------------
__global__ __launch_bounds__(256, 1)
void gemm_fuse_kernel(const float* __restrict__ V,
                      const float* __restrict__ S,
                      float* __restrict__ out) {
    extern __shared__ char smem[];
    const uint32_t smem_base = smem_u32(smem);
    float* rowAcc = (float*)smem;               // 128 floats, below tile area

    const int tid  = threadIdx.x;
    const int wid  = tid >> 5;
    const int lane = tid & 31;
    const int warp_m = wid & 1;                 // 2 x 64 rows
    const int warp_n = wid >> 1;                // 4 x 64 cols

    const int colBase = blockIdx.x * TN;        // 0..1280 within Wcat
    const int rowBase = blockIdx.y * TM;        // 0..384
    const int seg     = blockIdx.z >> 1;        // 0: hi*hi, 1: hi*lo, 2: lo*hi
    const int kOff0   = (blockIdx.z & 1) * KHALF;
    const __nv_bfloat16* Asrc = (seg < 2) ? g_s_hi : g_s_lo;
    const __nv_bfloat16* Bsrc = (seg == 1) ? g_W_lo : g_W_hi;

    if (tid < TM) rowAcc[tid] = 0.0f;

#pragma unroll
    for (int p = 0; p < STAGES - 1; p++) {
        uint32_t sA = smem_base + SMEM_TILES_OFF + p * STAGE_BYTES;
        load_stage(sA, sA + A_TILE_BYTES, Asrc, Bsrc, rowBase, colBase,
                   kOff0 + p * TK, tid);
    }

    float acc[4][8][4] = {};                    // [m16 tile][n8 tile][frag]

    const int rowA = lane & 15, colSelA = lane >> 4;
    const int rowB = ((lane >> 4) << 3) + (lane & 7), colSelB = (lane >> 3) & 1;

    for (int it = 0; it < CHUNKS_PER; it++) {
        if (it < CHUNKS_PER - 1) CP_WAIT(1);
        else                     CP_WAIT(0);
        __syncthreads();

        int nx = it + STAGES - 1;
        if (nx < CHUNKS_PER) {
            uint32_t nA = smem_base + SMEM_TILES_OFF + (nx % STAGES) * STAGE_BYTES;
            load_stage(nA, nA + A_TILE_BYTES, Asrc, Bsrc, rowBase, colBase,
                       kOff0 + nx * TK, tid);
        }

        const uint32_t sA = smem_base + SMEM_TILES_OFF + (it % STAGES) * STAGE_BYTES;
        const uint32_t sB = sA + A_TILE_BYTES;

#pragma unroll
        for (int ks = 0; ks < 4; ks++) {
            uint32_t a[4][4];
            uint32_t b[4][4];
#pragma unroll
            for (int mi = 0; mi < 4; mi++) {
                uint32_t addr = sA + SWZ((64 * warp_m + 16 * mi + rowA) * 128
                                         + (2 * ks + colSelA) * 16);
                LDSM_X4(a[mi], addr);
            }
#pragma unroll
            for (int q = 0; q < 4; q++) {
                uint32_t addr = sB + SWZ((64 * warp_n + 16 * q + rowB) * 128
                                         + (2 * ks + colSelB) * 16);
                LDSM_X4(b[q], addr);
            }
#pragma unroll
            for (int mi = 0; mi < 4; mi++)
#pragma unroll
                for (int nj = 0; nj < 8; nj++) {
                    uint32_t b0 = b[nj >> 1][(nj & 1) * 2 + 0];
                    uint32_t b1 = b[nj >> 1][(nj & 1) * 2 + 1];
                    MMA_BF16(acc[mi][nj], a[mi], b0, b1);
                }
        }
    }

    // --- epilogue 1: C . v_x, reduce into logits ---
    const int iBase = (colBase % D) + 64 * warp_n;
    const int kIdx  = colBase / D;              // head boundary clean (256 | 768)

    float rs[4][2] = {};
#pragma unroll
    for (int mi = 0; mi < 4; mi++) {
        int r0 = rowBase + 64 * warp_m + 16 * mi + (lane >> 2);
#pragma unroll
        for (int nj = 0; nj < 8; nj++) {
            const float2* v0 = (const float2*)(V + (size_t)r0 * D + iBase
                                               + 8 * nj + 2 * (lane & 3));
            const float2* v1 = (const float2*)(V + (size_t)(r0 + 8) * D + iBase
                                               + 8 * nj + 2 * (lane & 3));
            float2 x0 = *v0, x1 = *v1;
            rs[mi][0] = fmaf(acc[mi][nj][0], x0.x, rs[mi][0]);
            rs[mi][0] = fmaf(acc[mi][nj][1], x0.y, rs[mi][0]);
            rs[mi][1] = fmaf(acc[mi][nj][2], x1.x, rs[mi][1]);
            rs[mi][1] = fmaf(acc[mi][nj][3], x1.y, rs[mi][1]);
        }
    }
#pragma unroll
    for (int mi = 0; mi < 4; mi++)
#pragma unroll
        for (int h = 0; h < 2; h++) {
            rs[mi][h] += __shfl_xor_sync(0xffffffff, rs[mi][h], 1);
            rs[mi][h] += __shfl_xor_sync(0xffffffff, rs[mi][h], 2);
        }
    if ((lane & 3) == 0) {
#pragma unroll
        for (int mi = 0; mi < 4; mi++) {
            int lr = 64 * warp_m + 16 * mi + (lane >> 2);
            atomicAdd(&rowAcc[lr],     rs[mi][0]);
            atomicAdd(&rowAcc[lr + 8], rs[mi][1]);
        }
    }
    __syncthreads();
    if (tid < TM)
        atomicAdd(&g_logits[(rowBase + tid) * 2 + kIdx], rowAcc[tid]);

    // --- device-wide barrier (all 144 CTAs are co-resident: 1/SM) ---
    __threadfence();
    __syncthreads();
    if (tid == 0) {
        atomicAdd(&g_sync, 1);
        while (*(volatile int*)&g_sync != NCTA) { }
    }
    __syncthreads();
    __threadfence();

    // --- epilogue 2: softmax(2 logits) + fused combine, strided over grid ---
    const int ctaLin = (blockIdx.z * gridDim.y + blockIdx.y) * gridDim.x + blockIdx.x;
    const int gt = ctaLin * 256 + tid;
    const int stride = NCTA * 256;              // 36864
#pragma unroll
    for (int i = 0; i < 3; i++) {
        int idx = gt + i * stride;
        if (idx >= B * D / 4) break;
        int b = idx / (D / 4);
        float l0 = g_logits[b * 2 + 0];
        float l1 = g_logits[b * 2 + 1];
        float mx = fmaxf(l0, l1);
        float e0 = expf(l0 - mx);
        float e1 = expf(l1 - mx);
        float inv = 1.0f / (e0 + e1);
        float wa = e0 * inv;
        float wb = e1 * inv;
        float4 v = ((const float4*)V)[idx];
        float4 s = ((const float4*)S)[idx];
        float4 o;
        o.x = wa * v.x + wb * s.x;
        o.y = wa * v.y + wb * s.y;
        o.z = wa * v.z + wb * s.z;
        o.w = wa * v.w + wb * s.w;
        ((float4*)out)[idx] = o;
    }
}

// ---------------------------------------------------------------------------
// Entry point
// ---------------------------------------------------------------------------
extern "C" void kernel_launch(void* const* d_in, const int* in_sizes, int n_in,
                              void* d_out, int out_size) {
    const float* v_x  = (const float*)d_in[0];
    const float* s_x  = (const float*)d_in[1];
    const float* fc_w = (const float*)d_in[2];
    const float* fc_b = (const float*)d_in[3];
    float* out = (float*)d_out;

    cudaFuncSetAttribute(gemm_fuse_kernel,
                         cudaFuncAttributeMaxDynamicSharedMemorySize, SMEM_TOTAL);

    // 1) split + bias init + sync reset: 196608 threads, 8 floats each
    split_kernel<<<768, 256>>>((const float4*)fc_w, (const float4*)s_x, fc_b);

    // 2) fused HMMA GEMM + dot-reduce + grid barrier + softmax/combine
    dim3 grid(NTOT / TN, B / TM, 6);   // (6, 4, 6) = 144 CTAs
    gemm_fuse_kernel<<<grid, 256, SMEM_TOTAL>>>(v_x, s_x, out);
}